// round 3
// baseline (speedup 1.0000x reference)
#include <cuda_runtime.h>
#include <cuda_bf16.h>
#include <mma.h>
#include <cstdint>

using namespace nvcuda;

// ---------------- problem constants ----------------
#define BATCH     4
#define LQ        4096            // 64*64
#define EMB       512
#define HEADS     8
#define HDIM      64
#define FFN       2048
#define KVLEN     21504           // 16384 + 4096 + 1024
#define NKEY      6

// ---------------- pooled scratch (lifetime-aliased; 400 MB total) ----------------
// [0,              44040192)  K  (alive: KV gemms .. attention)   then reused as h (FFN)
// [44040192,       88080384)  V  (alive: KV gemms .. attention)
// [88080384,       96468992)  q  (alive: Qproj .. attention)      then reused as attn (in-place)
// [96468992,      104857600)  x  (alive: Wp gemm .. end)
#define OFF_K 0L
#define OFF_V 44040192L
#define OFF_Q 88080384L
#define OFF_X 96468992L
__device__ float sc_pool[104857600];

// ---------------- cp.async helpers ----------------
__device__ __forceinline__ void cp16(uint32_t dst, const void* src) {
    asm volatile("cp.async.cg.shared.global [%0], [%1], 16;" :: "r"(dst), "l"(src));
}
__device__ __forceinline__ void cp_commit() {
    asm volatile("cp.async.commit_group;");
}
template <int N> __device__ __forceinline__ void cp_wait() {
    asm volatile("cp.async.wait_group %0;" :: "n"(N));
}

// ---------------- GEMM: C = A[MxK] @ W[KxN] + bias, templated epilogue ----------------
// tile 128x128x32, 256 threads, 8 warps (4x2), warp does 32x64 via 2x4 tf32 wmma frags.
// Double-buffered cp.async staging for both operands.
#define BM 128
#define BN 128
#define BK 32
#define LDA 40     // 32 + 8 pad
#define LDB 136    // 128 + 8 pad
#define LDO 20     // 16 + 4 pad

#define SMEM_A_STG (BM * LDA)          // 5120 floats
#define SMEM_B_STG (BK * LDB)          // 4352 floats
#define SMEM_FLOATS (2 * SMEM_A_STG + 2 * SMEM_B_STG)   // 18944 floats = 75776 B

enum { EP_PLAIN = 0, EP_KV = 1, EP_RES = 2, EP_RELU = 3 };

template <int MODE>
__global__ void __launch_bounds__(256, 1)
gemm_tf32(const float* __restrict__ A, const float* __restrict__ W,
          const float* __restrict__ bias, float* __restrict__ C,
          int M, int N, int K,
          const float* __restrict__ res,   // EP_RES
          float* __restrict__ Vout,        // EP_KV (C = K-buffer)
          int Lf, int kvoff)               // EP_KV
{
    extern __shared__ float smem[];
    float* sA = smem;                       // 2 stages
    float* sB = smem + 2 * SMEM_A_STG;      // 2 stages

    const int tid  = threadIdx.x;
    const int warp = tid >> 5, lane = tid & 31;
    const int wm = warp & 3, wn = warp >> 2;   // 4 row-groups x 2 col-groups
    const long rowBase = (long)blockIdx.y * BM;
    const int  colBase = blockIdx.x * BN;

    // per-thread staging coordinates (4 x 16B chunks each for A and B)
    const int ar = tid >> 3, ac4 = tid & 7;    // A: rows tid>>3 + i*32? no: f = tid + i*256
    (void)ar; (void)ac4;

    wmma::fragment<wmma::accumulator, 16, 16, 8, float> acc[2][4];
#pragma unroll
    for (int i = 0; i < 2; i++)
#pragma unroll
        for (int j = 0; j < 4; j++) wmma::fill_fragment(acc[i][j], 0.0f);

    const int T = K / BK;

    auto issue = [&](int kt, int stg) {
#pragma unroll
        for (int i = 0; i < 4; i++) {               // A tile: 128x32 = 1024 chunks
            int f = tid + i * 256;
            int r = f >> 3, c4 = f & 7;
            uint32_t d = (uint32_t)__cvta_generic_to_shared(
                sA + stg * SMEM_A_STG + r * LDA + c4 * 4);
            cp16(d, A + (rowBase + r) * (long)K + kt + c4 * 4);
        }
#pragma unroll
        for (int i = 0; i < 4; i++) {               // B tile: 32x128 = 1024 chunks
            int f = tid + i * 256;
            int r = f >> 5, c4 = f & 31;
            uint32_t d = (uint32_t)__cvta_generic_to_shared(
                sB + stg * SMEM_B_STG + r * LDB + c4 * 4);
            cp16(d, W + (long)(kt + r) * N + colBase + c4 * 4);
        }
        cp_commit();
    };

    issue(0, 0);

    for (int t = 0; t < T; t++) {
        const int stg = t & 1;
        if (t + 1 < T) { issue((t + 1) * BK, stg ^ 1); cp_wait<1>(); }
        else           { cp_wait<0>(); }
        __syncthreads();

        const float* cA = sA + stg * SMEM_A_STG;
        const float* cB = sB + stg * SMEM_B_STG;
#pragma unroll
        for (int ks = 0; ks < BK; ks += 8) {
            wmma::fragment<wmma::matrix_a, 16, 16, 8, wmma::precision::tf32, wmma::row_major> af[2];
            wmma::fragment<wmma::matrix_b, 16, 16, 8, wmma::precision::tf32, wmma::row_major> bf[4];
#pragma unroll
            for (int i = 0; i < 2; i++) {
                wmma::load_matrix_sync(af[i], cA + (wm * 32 + i * 16) * LDA + ks, LDA);
#pragma unroll
                for (int u = 0; u < af[i].num_elements; u++)
                    af[i].x[u] = wmma::__float_to_tf32(af[i].x[u]);
            }
#pragma unroll
            for (int j = 0; j < 4; j++) {
                wmma::load_matrix_sync(bf[j], cB + ks * LDB + wn * 64 + j * 16, LDB);
#pragma unroll
                for (int u = 0; u < bf[j].num_elements; u++)
                    bf[j].x[u] = wmma::__float_to_tf32(bf[j].x[u]);
            }
#pragma unroll
            for (int i = 0; i < 2; i++)
#pragma unroll
                for (int j = 0; j < 4; j++)
                    wmma::mma_sync(acc[i][j], af[i], bf[j], acc[i][j]);
        }
        __syncthreads();   // guard stage reuse by next issue
    }

    // ---- epilogue: spill each 16x16 frag through per-warp smem, fuse tail op ----
    float* buf = smem + warp * 16 * LDO;   // reuse staging smem (all reads complete)
#pragma unroll
    for (int i = 0; i < 2; i++)
#pragma unroll
        for (int j = 0; j < 4; j++) {
            wmma::store_matrix_sync(buf, acc[i][j], LDO, wmma::mem_row_major);
            __syncwarp();
#pragma unroll
            for (int k = 0; k < 8; k++) {
                int e = lane + k * 32;            // 256 elems / 32 lanes
                int r = e >> 4, c = e & 15;
                long gr = rowBase + wm * 32 + i * 16 + r;
                int  gc = colBase + wn * 64 + j * 16 + c;
                float val = buf[r * LDO + c] + bias[gc];
                if (MODE == EP_PLAIN) {
                    C[gr * N + gc] = val;
                } else if (MODE == EP_RELU) {
                    C[gr * N + gc] = fmaxf(val, 0.0f);
                } else if (MODE == EP_RES) {
                    C[gr * N + gc] = val + res[gr * N + gc];
                } else {                           // EP_KV: N==1024, split halves
                    long b    = gr / Lf;
                    long irow = gr - b * Lf;
                    long drow = b * KVLEN + kvoff + irow;
                    if (gc < EMB) C[drow * EMB + gc]            = val;
                    else          Vout[drow * EMB + (gc - EMB)] = val;
                }
            }
            __syncwarp();
        }
}

// ---------------- gathered linear attention (in-place over q) ----------------
// one block per (b,l): 8 warps = 8 heads; lane owns 2 contiguous dims (float2).
// out may alias q: each thread reads its q element first, writes same offset last.
__global__ void __launch_bounds__(256, 8)
attn_kernel(const float* __restrict__ q, const float* __restrict__ Kb,
            const float* __restrict__ Vb, const int* __restrict__ idx,
            float* __restrict__ out)
{
    const int blk  = blockIdx.x;           // b*LQ + l
    const int b    = blk >> 12;            // LQ = 4096
    const int l    = blk & 4095;
    const int warp = threadIdx.x >> 5;     // head
    const int lane = threadIdx.x & 31;

    const float2 qv = *(const float2*)(q + (long)blk * EMB + warp * HDIM + lane * 2);
    float a0 = 0.0f, a1 = 0.0f;
    const long kvbase = (long)b * KVLEN;

#pragma unroll
    for (int kk = 0; kk < NKEY; kk++) {
        const int id = idx[l * NKEY + kk];
        const long off = (kvbase + id) * EMB + warp * HDIM + lane * 2;
        const float2 kv = *(const float2*)(Kb + off);
        float p = qv.x * kv.x + qv.y * kv.y;
        p += __shfl_xor_sync(0xFFFFFFFFu, p, 16);
        p += __shfl_xor_sync(0xFFFFFFFFu, p, 8);
        p += __shfl_xor_sync(0xFFFFFFFFu, p, 4);
        p += __shfl_xor_sync(0xFFFFFFFFu, p, 2);
        p += __shfl_xor_sync(0xFFFFFFFFu, p, 1);
        const float2 vv = *(const float2*)(Vb + off);
        a0 += p * vv.x;
        a1 += p * vv.y;
    }
    *(float2*)(out + (long)blk * EMB + warp * HDIM + lane * 2) = make_float2(a0, a1);
}

// ---------------- launch ----------------
extern "C" void kernel_launch(void* const* d_in, const int* in_sizes, int n_in,
                              void* d_out, int out_size)
{
    const float* tgt   = (const float*)d_in[0];
    const float* feat0 = (const float*)d_in[1];
    const float* feat1 = (const float*)d_in[2];
    const float* feat2 = (const float*)d_in[3];
    const int*   aidx  = (const int*)  d_in[4];
    const float* Wq  = (const float*)d_in[5];  const float* bq  = (const float*)d_in[6];
    const float* Wk0 = (const float*)d_in[7];  const float* bk0 = (const float*)d_in[8];
    const float* Wk1 = (const float*)d_in[9];  const float* bk1 = (const float*)d_in[10];
    const float* Wk2 = (const float*)d_in[11]; const float* bk2 = (const float*)d_in[12];
    const float* Wp  = (const float*)d_in[13]; const float* bp  = (const float*)d_in[14];
    const float* W1  = (const float*)d_in[15]; const float* b1  = (const float*)d_in[16];
    const float* W2  = (const float*)d_in[17]; const float* b2  = (const float*)d_in[18];
    float* out = (float*)d_out;

    float* pool;
    cudaGetSymbolAddress((void**)&pool, sc_pool);
    float* g_K    = pool + OFF_K;
    float* g_V    = pool + OFF_V;
    float* g_q    = pool + OFF_Q;      // attention output aliases q (in-place)
    float* g_attn = pool + OFF_Q;
    float* g_x    = pool + OFF_X;
    float* g_h    = pool + OFF_K;      // h reuses K region (dead after attention)

    const size_t SMEM_BYTES = SMEM_FLOATS * sizeof(float);   // 75776
    cudaFuncSetAttribute(gemm_tf32<EP_PLAIN>, cudaFuncAttributeMaxDynamicSharedMemorySize, (int)SMEM_BYTES);
    cudaFuncSetAttribute(gemm_tf32<EP_KV>,    cudaFuncAttributeMaxDynamicSharedMemorySize, (int)SMEM_BYTES);
    cudaFuncSetAttribute(gemm_tf32<EP_RES>,   cudaFuncAttributeMaxDynamicSharedMemorySize, (int)SMEM_BYTES);
    cudaFuncSetAttribute(gemm_tf32<EP_RELU>,  cudaFuncAttributeMaxDynamicSharedMemorySize, (int)SMEM_BYTES);

    const dim3 T(256);
    const int MROW = BATCH * LQ;   // 16384

    // q = tgt @ Wq + bq
    gemm_tf32<EP_PLAIN><<<dim3(EMB / BN, MROW / BM), T, SMEM_BYTES>>>(
        tgt, Wq, bq, g_q, MROW, EMB, EMB, nullptr, nullptr, 0, 0);

    // kv projections -> scatter into concatenated K/V
    gemm_tf32<EP_KV><<<dim3(1024 / BN, (BATCH * 16384) / BM), T, SMEM_BYTES>>>(
        feat0, Wk0, bk0, g_K, BATCH * 16384, 1024, 256, nullptr, g_V, 16384, 0);
    gemm_tf32<EP_KV><<<dim3(1024 / BN, (BATCH * 4096) / BM), T, SMEM_BYTES>>>(
        feat1, Wk1, bk1, g_K, BATCH * 4096, 1024, 512, nullptr, g_V, 4096, 16384);
    gemm_tf32<EP_KV><<<dim3(1024 / BN, (BATCH * 1024) / BM), T, SMEM_BYTES>>>(
        feat2, Wk2, bk2, g_K, BATCH * 1024, 1024, 1024, nullptr, g_V, 1024, 20480);

    // gathered linear attention (writes in-place over q)
    attn_kernel<<<BATCH * LQ, 256>>>(g_q, g_K, g_V, aidx, g_attn);

    // x = tgt + attn @ Wp + bp
    gemm_tf32<EP_RES><<<dim3(EMB / BN, MROW / BM), T, SMEM_BYTES>>>(
        g_attn, Wp, bp, g_x, MROW, EMB, EMB, tgt, nullptr, 0, 0);

    // h = relu(x @ W1 + b1)   (h aliases dead K region)
    gemm_tf32<EP_RELU><<<dim3(FFN / BN, MROW / BM), T, SMEM_BYTES>>>(
        g_x, W1, b1, g_h, MROW, FFN, EMB, nullptr, nullptr, 0, 0);

    // out = x + h @ W2 + b2
    gemm_tf32<EP_RES><<<dim3(EMB / BN, MROW / BM), T, SMEM_BYTES>>>(
        g_h, W2, b2, out, MROW, EMB, FFN, g_x, nullptr, 0, 0);
}

// round 6
// speedup vs baseline: 1.1000x; 1.1000x over previous
#include <cuda_runtime.h>
#include <cuda_bf16.h>
#include <mma.h>
#include <cstdint>

using namespace nvcuda;

// ---------------- problem constants ----------------
#define BATCH     4
#define LQ        4096            // 64*64
#define EMB       512
#define HEADS     8
#define HDIM      64
#define FFN       2048
#define KVLEN     21504           // 16384 + 4096 + 1024
#define NKEY      6

// ---------------- pooled scratch (lifetime-aliased; 400 MB total) ----------------
// [OFF_K ..) K  (alive: KV gemms .. attention) then reused as h (FFN hidden)
// [OFF_V ..) V  (alive: KV gemms .. attention)
// [OFF_Q ..) q  (alive: Qproj .. attention)    attention output written in-place
// [OFF_X ..) x  (alive: Wp gemm .. end)
#define OFF_K 0L
#define OFF_V 44040192L
#define OFF_Q 88080384L
#define OFF_X 96468992L
__device__ float sc_pool[104857600];

// ---------------- cp.async helpers ----------------
__device__ __forceinline__ void cp16(uint32_t dst, const void* src) {
    asm volatile("cp.async.cg.shared.global [%0], [%1], 16;" :: "r"(dst), "l"(src));
}
__device__ __forceinline__ void cp_commit() {
    asm volatile("cp.async.commit_group;");
}
template <int N> __device__ __forceinline__ void cp_wait() {
    asm volatile("cp.async.wait_group %0;" :: "n"(N));
}

// ---------------- GEMM: C = A[MxK] @ W[KxN] + bias, templated epilogue ----------------
// tile 128x64x32, 256 threads, 8 warps (4x2), warp tile 32x32 via 2x2 tf32 wmma frags.
// 2-stage cp.async pipeline (structure identical to the proven-passing kernel),
// __launch_bounds__(256,2) for 2 CTAs/SM -> 16 warps/SM.
#define BM 128
#define BN 64
#define BK 32
#define LDA 40     // 32 + 8 pad  (row = 160B, 16B-aligned)
#define LDB 72     // 64 + 8 pad  (row = 288B, 16B-aligned)
#define LDO 20     // 16 + 4 pad

#define SMEM_A_STG (BM * LDA)          // 5120 floats
#define SMEM_B_STG (BK * LDB)          // 2304 floats
#define SMEM_FLOATS (2 * (SMEM_A_STG + SMEM_B_STG))   // 14848 floats = 59392 B

enum { EP_PLAIN = 0, EP_KV = 1, EP_RES = 2, EP_RELU = 3 };

template <int MODE>
__global__ void __launch_bounds__(256, 2)
gemm_tf32(const float* __restrict__ A, const float* __restrict__ W,
          const float* __restrict__ bias, float* __restrict__ C,
          int M, int N, int K,
          const float* __restrict__ res,   // EP_RES
          float* __restrict__ Vout,        // EP_KV (C = K-buffer)
          int lgL, int kvoff)              // EP_KV: Lf = 1<<lgL
{
    extern __shared__ float smem[];

    const int tid  = threadIdx.x;
    const int warp = tid >> 5, lane = tid & 31;
    const int wm = warp & 3, wn = warp >> 2;     // 4x2 warp grid; warp tile 32x32
    const long rowBase = (long)blockIdx.y * BM;
    const int  colBase = blockIdx.x * BN;

    wmma::fragment<wmma::accumulator, 16, 16, 8, float> acc[2][2];
#pragma unroll
    for (int i = 0; i < 2; i++)
#pragma unroll
        for (int j = 0; j < 2; j++) wmma::fill_fragment(acc[i][j], 0.0f);

    const int T = K / BK;    // >= 8 for all our shapes

    auto issue = [&](int kt, int stg) {
        float* dA = smem + stg * (SMEM_A_STG + SMEM_B_STG);
        float* dB = dA + SMEM_A_STG;
#pragma unroll
        for (int i = 0; i < 4; i++) {               // A tile: 128x32 = 1024 float4
            int f = tid + i * 256;
            int r = f >> 3, c4 = f & 7;
            uint32_t d = (uint32_t)__cvta_generic_to_shared(dA + r * LDA + c4 * 4);
            cp16(d, A + (rowBase + r) * (long)K + kt + c4 * 4);
        }
#pragma unroll
        for (int i = 0; i < 2; i++) {               // B tile: 32x64 = 512 float4
            int f = tid + i * 256;
            int r = f >> 4, c4 = f & 15;
            uint32_t d = (uint32_t)__cvta_generic_to_shared(dB + r * LDB + c4 * 4);
            cp16(d, W + (long)(kt + r) * N + colBase + c4 * 4);
        }
        cp_commit();
    };

    issue(0, 0);

    for (int t = 0; t < T; t++) {
        const int stg = t & 1;
        if (t + 1 < T) { issue((t + 1) * BK, stg ^ 1); cp_wait<1>(); }
        else           { cp_wait<0>(); }
        __syncthreads();

        const float* cA = smem + stg * (SMEM_A_STG + SMEM_B_STG);
        const float* cB = cA + SMEM_A_STG;

#pragma unroll
        for (int ks = 0; ks < BK; ks += 8) {
            wmma::fragment<wmma::matrix_a, 16, 16, 8, wmma::precision::tf32, wmma::row_major> af[2];
            wmma::fragment<wmma::matrix_b, 16, 16, 8, wmma::precision::tf32, wmma::row_major> bf[2];
#pragma unroll
            for (int i = 0; i < 2; i++) {
                wmma::load_matrix_sync(af[i], cA + (wm * 32 + i * 16) * LDA + ks, LDA);
#pragma unroll
                for (int u = 0; u < af[i].num_elements; u++)
                    af[i].x[u] = wmma::__float_to_tf32(af[i].x[u]);
            }
#pragma unroll
            for (int j = 0; j < 2; j++) {
                wmma::load_matrix_sync(bf[j], cB + ks * LDB + wn * 32 + j * 16, LDB);
#pragma unroll
                for (int u = 0; u < bf[j].num_elements; u++)
                    bf[j].x[u] = wmma::__float_to_tf32(bf[j].x[u]);
            }
#pragma unroll
            for (int i = 0; i < 2; i++)
#pragma unroll
                for (int j = 0; j < 2; j++)
                    wmma::mma_sync(acc[i][j], af[i], bf[j], acc[i][j]);
        }
        __syncthreads();   // guard stage reuse by next issue
    }

    // ---- epilogue: spill each 16x16 frag through per-warp smem, fuse tail op, float4 I/O ----
    float* buf = smem + warp * 16 * LDO;   // all mainloop smem reads complete
#pragma unroll
    for (int i = 0; i < 2; i++)
#pragma unroll
        for (int j = 0; j < 2; j++) {
            wmma::store_matrix_sync(buf, acc[i][j], LDO, wmma::mem_row_major);
            __syncwarp();
#pragma unroll
            for (int k = 0; k < 2; k++) {
                int e = lane + k * 32;           // 64 float4 per 16x16 frag
                int r = e >> 2, c4 = (e & 3) * 4;
                long gr = rowBase + wm * 32 + i * 16 + r;
                int  gc = colBase + wn * 32 + j * 16 + c4;
                float4 v = *(const float4*)(buf + r * LDO + c4);
                float4 bb = *(const float4*)(bias + gc);
                v.x += bb.x; v.y += bb.y; v.z += bb.z; v.w += bb.w;
                if (MODE == EP_PLAIN) {
                    *(float4*)(C + gr * N + gc) = v;
                } else if (MODE == EP_RELU) {
                    v.x = fmaxf(v.x, 0.f); v.y = fmaxf(v.y, 0.f);
                    v.z = fmaxf(v.z, 0.f); v.w = fmaxf(v.w, 0.f);
                    *(float4*)(C + gr * N + gc) = v;
                } else if (MODE == EP_RES) {
                    float4 rr = *(const float4*)(res + gr * N + gc);
                    v.x += rr.x; v.y += rr.y; v.z += rr.z; v.w += rr.w;
                    *(float4*)(C + gr * N + gc) = v;
                } else {                          // EP_KV: N==1024, halves split at 512
                    long b    = gr >> lgL;
                    long irow = gr & ((1L << lgL) - 1);
                    long drow = b * KVLEN + kvoff + irow;
                    if (gc < EMB) *(float4*)(C    + drow * EMB + gc)         = v;
                    else          *(float4*)(Vout + drow * EMB + (gc - EMB)) = v;
                }
            }
            __syncwarp();
        }
}

// ---------------- gathered linear attention (in-place over q) ----------------
__global__ void __launch_bounds__(256, 8)
attn_kernel(const float* __restrict__ q, const float* __restrict__ Kb,
            const float* __restrict__ Vb, const int* __restrict__ idx,
            float* __restrict__ out)
{
    const int blk  = blockIdx.x;           // b*LQ + l
    const int b    = blk >> 12;            // LQ = 4096
    const int l    = blk & 4095;
    const int warp = threadIdx.x >> 5;     // head
    const int lane = threadIdx.x & 31;

    const float2 qv = *(const float2*)(q + (long)blk * EMB + warp * HDIM + lane * 2);
    float a0 = 0.0f, a1 = 0.0f;
    const long kvbase = (long)b * KVLEN;

#pragma unroll
    for (int kk = 0; kk < NKEY; kk++) {
        const int id = idx[l * NKEY + kk];
        const long off = (kvbase + id) * EMB + warp * HDIM + lane * 2;
        const float2 kv = *(const float2*)(Kb + off);
        float p = qv.x * kv.x + qv.y * kv.y;
        p += __shfl_xor_sync(0xFFFFFFFFu, p, 16);
        p += __shfl_xor_sync(0xFFFFFFFFu, p, 8);
        p += __shfl_xor_sync(0xFFFFFFFFu, p, 4);
        p += __shfl_xor_sync(0xFFFFFFFFu, p, 2);
        p += __shfl_xor_sync(0xFFFFFFFFu, p, 1);
        const float2 vv = *(const float2*)(Vb + off);
        a0 += p * vv.x;
        a1 += p * vv.y;
    }
    *(float2*)(out + (long)blk * EMB + warp * HDIM + lane * 2) = make_float2(a0, a1);
}

// ---------------- launch ----------------
extern "C" void kernel_launch(void* const* d_in, const int* in_sizes, int n_in,
                              void* d_out, int out_size)
{
    const float* tgt   = (const float*)d_in[0];
    const float* feat0 = (const float*)d_in[1];
    const float* feat1 = (const float*)d_in[2];
    const float* feat2 = (const float*)d_in[3];
    const int*   aidx  = (const int*)  d_in[4];
    const float* Wq  = (const float*)d_in[5];  const float* bq  = (const float*)d_in[6];
    const float* Wk0 = (const float*)d_in[7];  const float* bk0 = (const float*)d_in[8];
    const float* Wk1 = (const float*)d_in[9];  const float* bk1 = (const float*)d_in[10];
    const float* Wk2 = (const float*)d_in[11]; const float* bk2 = (const float*)d_in[12];
    const float* Wp  = (const float*)d_in[13]; const float* bp  = (const float*)d_in[14];
    const float* W1  = (const float*)d_in[15]; const float* b1  = (const float*)d_in[16];
    const float* W2  = (const float*)d_in[17]; const float* b2  = (const float*)d_in[18];
    float* out = (float*)d_out;

    float* pool;
    cudaGetSymbolAddress((void**)&pool, sc_pool);
    float* g_K    = pool + OFF_K;
    float* g_V    = pool + OFF_V;
    float* g_q    = pool + OFF_Q;      // attention output aliases q (in-place)
    float* g_attn = pool + OFF_Q;
    float* g_x    = pool + OFF_X;
    float* g_h    = pool + OFF_K;      // h reuses K region (dead after attention)

    const size_t SMEM_BYTES = SMEM_FLOATS * sizeof(float);   // 59392
    cudaFuncSetAttribute(gemm_tf32<EP_PLAIN>, cudaFuncAttributeMaxDynamicSharedMemorySize, (int)SMEM_BYTES);
    cudaFuncSetAttribute(gemm_tf32<EP_KV>,    cudaFuncAttributeMaxDynamicSharedMemorySize, (int)SMEM_BYTES);
    cudaFuncSetAttribute(gemm_tf32<EP_RES>,   cudaFuncAttributeMaxDynamicSharedMemorySize, (int)SMEM_BYTES);
    cudaFuncSetAttribute(gemm_tf32<EP_RELU>,  cudaFuncAttributeMaxDynamicSharedMemorySize, (int)SMEM_BYTES);

    const dim3 T(256);
    const int MROW = BATCH * LQ;   // 16384

    // q = tgt @ Wq + bq
    gemm_tf32<EP_PLAIN><<<dim3(EMB / BN, MROW / BM), T, SMEM_BYTES>>>(
        tgt, Wq, bq, g_q, MROW, EMB, EMB, nullptr, nullptr, 0, 0);

    // kv projections -> scatter into concatenated K/V
    gemm_tf32<EP_KV><<<dim3(1024 / BN, (BATCH * 16384) / BM), T, SMEM_BYTES>>>(
        feat0, Wk0, bk0, g_K, BATCH * 16384, 1024, 256, nullptr, g_V, 14, 0);
    gemm_tf32<EP_KV><<<dim3(1024 / BN, (BATCH * 4096) / BM), T, SMEM_BYTES>>>(
        feat1, Wk1, bk1, g_K, BATCH * 4096, 1024, 512, nullptr, g_V, 12, 16384);
    gemm_tf32<EP_KV><<<dim3(1024 / BN, (BATCH * 1024) / BM), T, SMEM_BYTES>>>(
        feat2, Wk2, bk2, g_K, BATCH * 1024, 1024, 1024, nullptr, g_V, 10, 20480);

    // gathered linear attention (writes in-place over q)
    attn_kernel<<<BATCH * LQ, 256>>>(g_q, g_K, g_V, aidx, g_attn);

    // x = tgt + attn @ Wp + bp
    gemm_tf32<EP_RES><<<dim3(EMB / BN, MROW / BM), T, SMEM_BYTES>>>(
        g_attn, Wp, bp, g_x, MROW, EMB, EMB, tgt, nullptr, 0, 0);

    // h = relu(x @ W1 + b1)   (h aliases dead K region)
    gemm_tf32<EP_RELU><<<dim3(FFN / BN, MROW / BM), T, SMEM_BYTES>>>(
        g_x, W1, b1, g_h, MROW, FFN, EMB, nullptr, nullptr, 0, 0);

    // out = x + h @ W2 + b2
    gemm_tf32<EP_RES><<<dim3(EMB / BN, MROW / BM), T, SMEM_BYTES>>>(
        g_h, W2, b2, out, MROW, EMB, FFN, g_x, nullptr, 0, 0);
}

// round 7
// speedup vs baseline: 1.2242x; 1.1129x over previous
#include <cuda_runtime.h>
#include <cuda_bf16.h>
#include <mma.h>
#include <cstdint>

using namespace nvcuda;

// ---------------- problem constants ----------------
#define BATCH     4
#define LQ        4096            // 64*64
#define EMB       512
#define HEADS     8
#define HDIM      64
#define FFN       2048
#define KVLEN     21504           // 16384 + 4096 + 1024
#define NKEY      6

// ---------------- pooled scratch (lifetime-aliased; 400 MB total) ----------------
// [OFF_K ..) K  (alive: KV gemms .. attention) then reused as h (FFN hidden)
// [OFF_V ..) V  (alive: KV gemms .. attention)
// [OFF_Q ..) q  (alive: Qproj .. attention)    attention output written in-place
// [OFF_X ..) x  (alive: Wp gemm .. end)
#define OFF_K 0L
#define OFF_V 44040192L
#define OFF_Q 88080384L
#define OFF_X 96468992L
__device__ float sc_pool[104857600];

// ---------------- cp.async helpers ----------------
__device__ __forceinline__ void cp16(uint32_t dst, const void* src) {
    asm volatile("cp.async.cg.shared.global [%0], [%1], 16;" :: "r"(dst), "l"(src));
}
__device__ __forceinline__ void cp_commit() {
    asm volatile("cp.async.commit_group;");
}
template <int N> __device__ __forceinline__ void cp_wait() {
    asm volatile("cp.async.wait_group %0;" :: "n"(N));
}

// ---------------- GEMM: C = A[MxK] @ W[KxN] + bias, templated epilogue ----------------
// CTA tile 256x128x32, 256 threads, 8 warps (4x2), warp tile 64x64 via 4x4 tf32 wmma frags.
// 2-stage cp.async pipeline (structure identical to the twice-passing kernel).
// FLOP/LDS doubled vs all prior rounds: per k=8 step, 8 fragment loads feed 16 wmma.
#define BM 256
#define BN 128
#define BK 32
#define LDA 40     // 32 + 8 pad  (row = 160B, 16B-aligned)
#define LDB 136    // 128 + 8 pad (row = 544B, 16B-aligned)
#define LDO 20     // 16 + 4 pad

#define SMEM_A_STG (BM * LDA)          // 10240 floats
#define SMEM_B_STG (BK * LDB)          // 4352 floats
#define SMEM_FLOATS (2 * (SMEM_A_STG + SMEM_B_STG))   // 29184 floats = 116736 B

enum { EP_PLAIN = 0, EP_KV = 1, EP_RES = 2, EP_RELU = 3 };

template <int MODE>
__global__ void __launch_bounds__(256, 1)
gemm_tf32(const float* __restrict__ A, const float* __restrict__ W,
          const float* __restrict__ bias, float* __restrict__ C,
          int M, int N, int K,
          const float* __restrict__ res,   // EP_RES
          float* __restrict__ Vout,        // EP_KV (C = K-buffer)
          int lgL, int kvoff)              // EP_KV: Lf = 1<<lgL
{
    extern __shared__ float smem[];

    const int tid  = threadIdx.x;
    const int warp = tid >> 5, lane = tid & 31;
    const int wm = warp & 3, wn = warp >> 2;     // 4x2 warp grid; warp tile 64x64
    const long rowBase = (long)blockIdx.y * BM;
    const int  colBase = blockIdx.x * BN;

    wmma::fragment<wmma::accumulator, 16, 16, 8, float> acc[4][4];
#pragma unroll
    for (int i = 0; i < 4; i++)
#pragma unroll
        for (int j = 0; j < 4; j++) wmma::fill_fragment(acc[i][j], 0.0f);

    const int T = K / BK;    // >= 8 for all our shapes

    auto issue = [&](int kt, int stg) {
        float* dA = smem + stg * (SMEM_A_STG + SMEM_B_STG);
        float* dB = dA + SMEM_A_STG;
#pragma unroll
        for (int i = 0; i < 8; i++) {               // A tile: 256x32 = 2048 float4
            int f = tid + i * 256;
            int r = f >> 3, c4 = f & 7;
            uint32_t d = (uint32_t)__cvta_generic_to_shared(dA + r * LDA + c4 * 4);
            cp16(d, A + (rowBase + r) * (long)K + kt + c4 * 4);
        }
#pragma unroll
        for (int i = 0; i < 4; i++) {               // B tile: 32x128 = 1024 float4
            int f = tid + i * 256;
            int r = f >> 5, c4 = f & 31;
            uint32_t d = (uint32_t)__cvta_generic_to_shared(dB + r * LDB + c4 * 4);
            cp16(d, W + (long)(kt + r) * N + colBase + c4 * 4);
        }
        cp_commit();
    };

    issue(0, 0);

    for (int t = 0; t < T; t++) {
        const int stg = t & 1;
        if (t + 1 < T) { issue((t + 1) * BK, stg ^ 1); cp_wait<1>(); }
        else           { cp_wait<0>(); }
        __syncthreads();

        const float* cA = smem + stg * (SMEM_A_STG + SMEM_B_STG);
        const float* cB = cA + SMEM_A_STG;

#pragma unroll
        for (int ks = 0; ks < BK; ks += 8) {
            wmma::fragment<wmma::matrix_a, 16, 16, 8, wmma::precision::tf32, wmma::row_major> af[4];
            wmma::fragment<wmma::matrix_b, 16, 16, 8, wmma::precision::tf32, wmma::row_major> bf;
#pragma unroll
            for (int i = 0; i < 4; i++) {
                wmma::load_matrix_sync(af[i], cA + (wm * 64 + i * 16) * LDA + ks, LDA);
#pragma unroll
                for (int u = 0; u < af[i].num_elements; u++)
                    af[i].x[u] = wmma::__float_to_tf32(af[i].x[u]);
            }
#pragma unroll
            for (int j = 0; j < 4; j++) {
                wmma::load_matrix_sync(bf, cB + ks * LDB + wn * 64 + j * 16, LDB);
#pragma unroll
                for (int u = 0; u < bf.num_elements; u++)
                    bf.x[u] = wmma::__float_to_tf32(bf.x[u]);
#pragma unroll
                for (int i = 0; i < 4; i++)
                    wmma::mma_sync(acc[i][j], af[i], bf, acc[i][j]);
            }
        }
        __syncthreads();   // guard stage reuse by next issue
    }

    // ---- epilogue: spill each 16x16 frag through per-warp smem, fuse tail op, float4 I/O ----
    float* buf = smem + warp * 16 * LDO;   // all mainloop smem reads complete
#pragma unroll
    for (int i = 0; i < 4; i++)
#pragma unroll
        for (int j = 0; j < 4; j++) {
            wmma::store_matrix_sync(buf, acc[i][j], LDO, wmma::mem_row_major);
            __syncwarp();
#pragma unroll
            for (int k = 0; k < 2; k++) {
                int e = lane + k * 32;           // 64 float4 per 16x16 frag
                int r = e >> 2, c4 = (e & 3) * 4;
                long gr = rowBase + wm * 64 + i * 16 + r;
                int  gc = colBase + wn * 64 + j * 16 + c4;
                float4 v = *(const float4*)(buf + r * LDO + c4);
                float4 bb = *(const float4*)(bias + gc);
                v.x += bb.x; v.y += bb.y; v.z += bb.z; v.w += bb.w;
                if (MODE == EP_PLAIN) {
                    *(float4*)(C + gr * N + gc) = v;
                } else if (MODE == EP_RELU) {
                    v.x = fmaxf(v.x, 0.f); v.y = fmaxf(v.y, 0.f);
                    v.z = fmaxf(v.z, 0.f); v.w = fmaxf(v.w, 0.f);
                    *(float4*)(C + gr * N + gc) = v;
                } else if (MODE == EP_RES) {
                    float4 rr = *(const float4*)(res + gr * N + gc);
                    v.x += rr.x; v.y += rr.y; v.z += rr.z; v.w += rr.w;
                    *(float4*)(C + gr * N + gc) = v;
                } else {                          // EP_KV: N==1024, halves split at 512
                    long b    = gr >> lgL;
                    long irow = gr & ((1L << lgL) - 1);
                    long drow = b * KVLEN + kvoff + irow;
                    if (gc < EMB) *(float4*)(C    + drow * EMB + gc)         = v;
                    else          *(float4*)(Vout + drow * EMB + (gc - EMB)) = v;
                }
            }
            __syncwarp();
        }
}

// ---------------- gathered linear attention (in-place over q) ----------------
__global__ void __launch_bounds__(256, 8)
attn_kernel(const float* __restrict__ q, const float* __restrict__ Kb,
            const float* __restrict__ Vb, const int* __restrict__ idx,
            float* __restrict__ out)
{
    const int blk  = blockIdx.x;           // b*LQ + l
    const int b    = blk >> 12;            // LQ = 4096
    const int l    = blk & 4095;
    const int warp = threadIdx.x >> 5;     // head
    const int lane = threadIdx.x & 31;

    const float2 qv = *(const float2*)(q + (long)blk * EMB + warp * HDIM + lane * 2);
    float a0 = 0.0f, a1 = 0.0f;
    const long kvbase = (long)b * KVLEN;

#pragma unroll
    for (int kk = 0; kk < NKEY; kk++) {
        const int id = idx[l * NKEY + kk];
        const long off = (kvbase + id) * EMB + warp * HDIM + lane * 2;
        const float2 kv = *(const float2*)(Kb + off);
        float p = qv.x * kv.x + qv.y * kv.y;
        p += __shfl_xor_sync(0xFFFFFFFFu, p, 16);
        p += __shfl_xor_sync(0xFFFFFFFFu, p, 8);
        p += __shfl_xor_sync(0xFFFFFFFFu, p, 4);
        p += __shfl_xor_sync(0xFFFFFFFFu, p, 2);
        p += __shfl_xor_sync(0xFFFFFFFFu, p, 1);
        const float2 vv = *(const float2*)(Vb + off);
        a0 += p * vv.x;
        a1 += p * vv.y;
    }
    *(float2*)(out + (long)blk * EMB + warp * HDIM + lane * 2) = make_float2(a0, a1);
}

// ---------------- launch ----------------
extern "C" void kernel_launch(void* const* d_in, const int* in_sizes, int n_in,
                              void* d_out, int out_size)
{
    const float* tgt   = (const float*)d_in[0];
    const float* feat0 = (const float*)d_in[1];
    const float* feat1 = (const float*)d_in[2];
    const float* feat2 = (const float*)d_in[3];
    const int*   aidx  = (const int*)  d_in[4];
    const float* Wq  = (const float*)d_in[5];  const float* bq  = (const float*)d_in[6];
    const float* Wk0 = (const float*)d_in[7];  const float* bk0 = (const float*)d_in[8];
    const float* Wk1 = (const float*)d_in[9];  const float* bk1 = (const float*)d_in[10];
    const float* Wk2 = (const float*)d_in[11]; const float* bk2 = (const float*)d_in[12];
    const float* Wp  = (const float*)d_in[13]; const float* bp  = (const float*)d_in[14];
    const float* W1  = (const float*)d_in[15]; const float* b1  = (const float*)d_in[16];
    const float* W2  = (const float*)d_in[17]; const float* b2  = (const float*)d_in[18];
    float* out = (float*)d_out;

    float* pool;
    cudaGetSymbolAddress((void**)&pool, sc_pool);
    float* g_K    = pool + OFF_K;
    float* g_V    = pool + OFF_V;
    float* g_q    = pool + OFF_Q;      // attention output aliases q (in-place)
    float* g_attn = pool + OFF_Q;
    float* g_x    = pool + OFF_X;
    float* g_h    = pool + OFF_K;      // h reuses K region (dead after attention)

    const size_t SMEM_BYTES = SMEM_FLOATS * sizeof(float);   // 116736
    cudaFuncSetAttribute(gemm_tf32<EP_PLAIN>, cudaFuncAttributeMaxDynamicSharedMemorySize, (int)SMEM_BYTES);
    cudaFuncSetAttribute(gemm_tf32<EP_KV>,    cudaFuncAttributeMaxDynamicSharedMemorySize, (int)SMEM_BYTES);
    cudaFuncSetAttribute(gemm_tf32<EP_RES>,   cudaFuncAttributeMaxDynamicSharedMemorySize, (int)SMEM_BYTES);
    cudaFuncSetAttribute(gemm_tf32<EP_RELU>,  cudaFuncAttributeMaxDynamicSharedMemorySize, (int)SMEM_BYTES);

    const dim3 T(256);
    const int MROW = BATCH * LQ;   // 16384

    // q = tgt @ Wq + bq
    gemm_tf32<EP_PLAIN><<<dim3(EMB / BN, MROW / BM), T, SMEM_BYTES>>>(
        tgt, Wq, bq, g_q, MROW, EMB, EMB, nullptr, nullptr, 0, 0);

    // kv projections -> scatter into concatenated K/V
    gemm_tf32<EP_KV><<<dim3(1024 / BN, (BATCH * 16384) / BM), T, SMEM_BYTES>>>(
        feat0, Wk0, bk0, g_K, BATCH * 16384, 1024, 256, nullptr, g_V, 14, 0);
    gemm_tf32<EP_KV><<<dim3(1024 / BN, (BATCH * 4096) / BM), T, SMEM_BYTES>>>(
        feat1, Wk1, bk1, g_K, BATCH * 4096, 1024, 512, nullptr, g_V, 12, 16384);
    gemm_tf32<EP_KV><<<dim3(1024 / BN, (BATCH * 1024) / BM), T, SMEM_BYTES>>>(
        feat2, Wk2, bk2, g_K, BATCH * 1024, 1024, 1024, nullptr, g_V, 10, 20480);

    // gathered linear attention (writes in-place over q)
    attn_kernel<<<BATCH * LQ, 256>>>(g_q, g_K, g_V, aidx, g_attn);

    // x = tgt + attn @ Wp + bp
    gemm_tf32<EP_RES><<<dim3(EMB / BN, MROW / BM), T, SMEM_BYTES>>>(
        g_attn, Wp, bp, g_x, MROW, EMB, EMB, tgt, nullptr, 0, 0);

    // h = relu(x @ W1 + b1)   (h aliases dead K region)
    gemm_tf32<EP_RELU><<<dim3(FFN / BN, MROW / BM), T, SMEM_BYTES>>>(
        g_x, W1, b1, g_h, MROW, FFN, EMB, nullptr, nullptr, 0, 0);

    // out = x + h @ W2 + b2
    gemm_tf32<EP_RES><<<dim3(EMB / BN, MROW / BM), T, SMEM_BYTES>>>(
        g_h, W2, b2, out, MROW, EMB, FFN, g_x, nullptr, 0, 0);
}